// round 2
// baseline (speedup 1.0000x reference)
#include <cuda_runtime.h>
#include <math.h>

#define B_SZ 2
#define L_SEQ 4352
#define DMODEL 768
#define DINNER 1536
#define DSTATE 128
#define NHEADS 24
#define HEADDIM 64
#define CONVDIM 1792
#define DPROJ 3352
#define IMG_N 4096
#define ROWS (B_SZ * L_SEQ)            // 8704
#define HEAD_ROWS (L_SEQ - IMG_N)      // 256
#define LN_EPS 1e-5f
#define K_CONV (25 * DMODEL)           // 19200

// ---------------- static scratch (no allocations allowed) ----------------
__device__ __align__(16) float g_u[ROWS * DMODEL];        // ln1 output
__device__ __align__(16) float g_zx[ROWS * DPROJ];        // in_proj output
__device__ __align__(16) float g_xbc[ROWS * CONVDIM];     // conv1d+silu output
__device__ float g_dt[ROWS * NHEADS];
__device__ float g_dA[ROWS * NHEADS];
__device__ __align__(16) float g_y[ROWS * DINNER];        // scan out / gated+normed
__device__ __align__(16) float g_h[ROWS * DMODEL];        // mamba block output
__device__ __align__(16) float g_img[B_SZ * IMG_N * DMODEL]; // ln2 output
__device__ __align__(16) float g_w2t[K_CONV * DMODEL];    // transposed conv2d weights

// ---------------- helpers ----------------
__device__ __forceinline__ float blockSum256(float v) {
    __shared__ float sh[8];
    __syncthreads();  // protect sh from previous use
#pragma unroll
    for (int o = 16; o; o >>= 1) v += __shfl_xor_sync(0xffffffffu, v, o);
    if ((threadIdx.x & 31) == 0) sh[threadIdx.x >> 5] = v;
    __syncthreads();
    float tot = 0.f;
#pragma unroll
    for (int i = 0; i < 8; i++) tot += sh[i];
    return tot;
}

// ---------------- LayerNorm 1 (x -> g_u) ----------------
__global__ void ln1_kernel(const float* __restrict__ x, const float* __restrict__ w,
                           const float* __restrict__ b) {
    int row = blockIdx.x;
    int tid = threadIdx.x;
    const float* xr = x + row * DMODEL;
    float v0 = xr[tid], v1 = xr[tid + 256], v2 = xr[tid + 512];
    float mean = blockSum256(v0 + v1 + v2) * (1.f / 768.f);
    float d0 = v0 - mean, d1 = v1 - mean, d2 = v2 - mean;
    float var = blockSum256(d0 * d0 + d1 * d1 + d2 * d2) * (1.f / 768.f);
    float rs = rsqrtf(var + LN_EPS);
    float* o = g_u + row * DMODEL;
    o[tid]       = d0 * rs * w[tid]       + b[tid];
    o[tid + 256] = d1 * rs * w[tid + 256] + b[tid + 256];
    o[tid + 512] = d2 * rs * w[tid + 512] + b[tid + 512];
}

// ---------------- LayerNorm 2 (g_h tail -> g_img) ----------------
__global__ void ln2_kernel(const float* __restrict__ w, const float* __restrict__ b) {
    int m = blockIdx.x;           // 0 .. B*IMG-1
    int tid = threadIdx.x;
    int bb = m >> 12, pix = m & (IMG_N - 1);
    const float* xr = g_h + (bb * L_SEQ + HEAD_ROWS + pix) * DMODEL;
    float v0 = xr[tid], v1 = xr[tid + 256], v2 = xr[tid + 512];
    float mean = blockSum256(v0 + v1 + v2) * (1.f / 768.f);
    float d0 = v0 - mean, d1 = v1 - mean, d2 = v2 - mean;
    float var = blockSum256(d0 * d0 + d1 * d1 + d2 * d2) * (1.f / 768.f);
    float rs = rsqrtf(var + LN_EPS);
    float* o = g_img + m * DMODEL;
    o[tid]       = d0 * rs * w[tid]       + b[tid];
    o[tid + 256] = d1 * rs * w[tid + 256] + b[tid + 256];
    o[tid + 512] = d2 * rs * w[tid + 512] + b[tid + 512];
}

// ---------------- generic tiled SGEMM: C[M,N] = A[M,K] @ B[K,N] ----------------
// M % 128 == 0, K % 8 == 0 required. N arbitrary (guarded).
__global__ __launch_bounds__(256) void sgemm_kernel(
    const float* __restrict__ A, const float* __restrict__ Bm,
    float* __restrict__ C, int M, int N, int K) {
    __shared__ __align__(16) float As[8][132];
    __shared__ __align__(16) float Bs[8][128];
    int tid = threadIdx.x;
    int bm = blockIdx.y * 128, bn = blockIdx.x * 128;
    int arow = tid >> 1, ac = (tid & 1) << 2;
    int brow = tid >> 5, bcol = (tid & 31) << 2;
    int ty = tid >> 4, tx = tid & 15;
    float acc[8][8];
#pragma unroll
    for (int i = 0; i < 8; i++)
#pragma unroll
        for (int j = 0; j < 8; j++) acc[i][j] = 0.f;
    const float* Ap = A + (bm + arow) * K + ac;
    bool nfull = (bn + 128 <= N);
    int col = bn + bcol;
    for (int k0 = 0; k0 < K; k0 += 8) {
        float4 av = *(const float4*)(Ap + k0);
        float4 bv = make_float4(0.f, 0.f, 0.f, 0.f);
        const float* Bp = Bm + (k0 + brow) * N;
        if (nfull || col + 3 < N) {
            bv = *(const float4*)(Bp + col);
        } else {
            if (col     < N) bv.x = Bp[col];
            if (col + 1 < N) bv.y = Bp[col + 1];
            if (col + 2 < N) bv.z = Bp[col + 2];
        }
        __syncthreads();
        As[ac][arow]     = av.x;
        As[ac + 1][arow] = av.y;
        As[ac + 2][arow] = av.z;
        As[ac + 3][arow] = av.w;
        *(float4*)&Bs[brow][bcol] = bv;
        __syncthreads();
#pragma unroll
        for (int kk = 0; kk < 8; ++kk) {
            float4 a0 = *(const float4*)&As[kk][ty * 8];
            float4 a1 = *(const float4*)&As[kk][ty * 8 + 4];
            float4 b0 = *(const float4*)&Bs[kk][tx * 8];
            float4 b1 = *(const float4*)&Bs[kk][tx * 8 + 4];
            float a[8] = {a0.x, a0.y, a0.z, a0.w, a1.x, a1.y, a1.z, a1.w};
            float bb[8] = {b0.x, b0.y, b0.z, b0.w, b1.x, b1.y, b1.z, b1.w};
#pragma unroll
            for (int i = 0; i < 8; i++)
#pragma unroll
                for (int j = 0; j < 8; j++) acc[i][j] += a[i] * bb[j];
        }
    }
#pragma unroll
    for (int i = 0; i < 8; i++) {
        int m = bm + ty * 8 + i;
        float* Cr = C + m * N;
        int c0 = bn + tx * 8;
        if (nfull || c0 + 7 < N) {
            float4 v0 = {acc[i][0], acc[i][1], acc[i][2], acc[i][3]};
            float4 v1 = {acc[i][4], acc[i][5], acc[i][6], acc[i][7]};
            *(float4*)(Cr + c0) = v0;
            *(float4*)(Cr + c0 + 4) = v1;
        } else {
            for (int j = 0; j < 8; j++)
                if (c0 + j < N) Cr[c0 + j] = acc[i][j];
        }
    }
}

// ---------------- depthwise causal conv1d + silu ----------------
__global__ void conv1d_kernel(const float* __restrict__ w, const float* __restrict__ bias) {
    int row = blockIdx.x;
    int b = row / L_SEQ;
    int l = row - b * L_SEQ;
    for (int c = threadIdx.x; c < CONVDIM; c += 256) {
        float acc = bias[c];
#pragma unroll
        for (int j = 0; j < 4; j++) {
            int ll = l - 3 + j;
            if (ll >= 0)
                acc += g_zx[(b * L_SEQ + ll) * DPROJ + DINNER + c] * w[c * 4 + j];
        }
        acc = acc / (1.f + expf(-acc));  // silu
        g_xbc[row * CONVDIM + c] = acc;
    }
}

// ---------------- dt = softplus(raw + bias), dA = exp(dt * -exp(A_log)) ----------------
__global__ void dtda_kernel(const float* __restrict__ dt_bias, const float* __restrict__ A_log) {
    int i = blockIdx.x * 256 + threadIdx.x;
    if (i >= ROWS * NHEADS) return;
    int row = i / NHEADS;
    int h = i - row * NHEADS;
    float v = g_zx[row * DPROJ + (DINNER + CONVDIM) + h] + dt_bias[h];
    float dtv = (v > 20.f) ? v : log1pf(expf(v));
    g_dt[i] = dtv;
    g_dA[i] = expf(-dtv * expf(A_log[h]));
}

// ---------------- selective scan ----------------
// grid (2, NHEADS, B), block 1024 = 32 warps. warp -> p; lane -> 4 consecutive n.
__global__ __launch_bounds__(1024) void scan_kernel(const float* __restrict__ Dskip) {
    int warp = threadIdx.x >> 5, lane = threadIdx.x & 31;
    int p = blockIdx.x * 32 + warp;
    int hh = blockIdx.y, b = blockIdx.z;
    int ch = hh * HEADDIM + p;
    float h0 = 0.f, h1 = 0.f, h2 = 0.f, h3 = 0.f;
    float Dh = Dskip[hh];
    int nb = lane * 4;
    for (int t = 0; t < L_SEQ; ++t) {
        int r = b * L_SEQ + t;
        int base = r * CONVDIM;
        float dAt = g_dA[r * NHEADS + hh];
        float dtt = g_dt[r * NHEADS + hh];
        float xs = g_xbc[base + ch];
        float dtx = dtt * xs;
        float4 Bv = *(const float4*)&g_xbc[base + DINNER + nb];
        float4 Cv = *(const float4*)&g_xbc[base + DINNER + DSTATE + nb];
        h0 = h0 * dAt + dtx * Bv.x;
        h1 = h1 * dAt + dtx * Bv.y;
        h2 = h2 * dAt + dtx * Bv.z;
        h3 = h3 * dAt + dtx * Bv.w;
        float part = h0 * Cv.x + h1 * Cv.y + h2 * Cv.z + h3 * Cv.w;
#pragma unroll
        for (int o = 16; o; o >>= 1) part += __shfl_xor_sync(0xffffffffu, part, o);
        if (lane == 0) g_y[r * DINNER + ch] = part + Dh * xs;
    }
}

// ---------------- y = y * silu(z); RMSNorm; * norm_w (in place on g_y) ----------------
__global__ void gate_rms_kernel(const float* __restrict__ norm_w) {
    int row = blockIdx.x;
    int tid = threadIdx.x;
    __shared__ float sh[DINNER];
    float ss = 0.f;
#pragma unroll
    for (int it = 0; it < 6; ++it) {
        int c = tid + it * 256;
        float z = g_zx[row * DPROJ + c];
        float yv = g_y[row * DINNER + c];
        float t = yv * (z / (1.f + expf(-z)));
        sh[c] = t;
        ss += t * t;
    }
    float tot = blockSum256(ss);
    float sc = rsqrtf(tot * (1.f / 1536.f) + LN_EPS);
#pragma unroll
    for (int it = 0; it < 6; ++it) {
        int c = tid + it * 256;
        g_y[row * DINNER + c] = sh[c] * sc * norm_w[c];
    }
}

// ---------------- head rows: out = x + h ----------------
__global__ void head_add_kernel(const float* __restrict__ x, float* __restrict__ out) {
    int row = blockIdx.x;                 // 0 .. B*HEAD_ROWS-1
    int b = row / HEAD_ROWS;
    int l = row - b * HEAD_ROWS;
    int g = (b * L_SEQ + l) * DMODEL;
    for (int c = threadIdx.x; c < DMODEL; c += 256)
        out[g + c] = x[g + c] + g_h[g + c];
}

// ---------------- conv2d weight transpose: w2t[tap*768+ci][co] ----------------
__global__ void wtrans_kernel(const float* __restrict__ w2) {
    int k = blockIdx.x;                   // 0 .. 19199 (tap-major)
    int tap = k / DMODEL;
    int ci = k - tap * DMODEL;
    const float* src = w2 + ci * 25 + tap;   // + n * 19200
    float* dst = g_w2t + k * DMODEL;
    for (int n = threadIdx.x; n < DMODEL; n += 256)
        dst[n] = src[n * K_CONV];
}

// ---------------- conv2d 5x5 SAME as implicit GEMM + bias + residual ----------------
// M = B*IMG = 8192, N = 768, K = 19200 = 25 taps x 768.  Tap-major K loop:
// boundary predicate + A base pointer computed once per tap (25x), inner 96
// k-tiles are pure load + FFMA. Writes tail rows of d_out directly.
__global__ __launch_bounds__(256) void conv2d_gemm_kernel(
    const float* __restrict__ x, const float* __restrict__ bias2,
    float* __restrict__ out) {
    __shared__ __align__(16) float As[8][132];
    __shared__ __align__(16) float Bs[8][128];
    int tid = threadIdx.x;
    int bm = blockIdx.y * 128, bn = blockIdx.x * 128;
    int arow = tid >> 1, ac = (tid & 1) << 2;
    int brow = tid >> 5, bcol = (tid & 31) << 2;
    int ty = tid >> 4, tx = tid & 15;
    float acc[8][8];
#pragma unroll
    for (int i = 0; i < 8; i++)
#pragma unroll
        for (int j = 0; j < 8; j++) acc[i][j] = 0.f;

    int m = bm + arow;
    int bi = m >> 12;
    int pix = m & (IMG_N - 1);
    int py = pix >> 6, px = pix & 63;

    const float* Bbase = g_w2t + brow * DMODEL + bn + bcol;

    for (int tap = 0; tap < 25; ++tap) {
        int ky = tap / 5, kx = tap - ky * 5;
        int iy = py + ky - 2, ix = px + kx - 2;
        bool ok = (iy >= 0) && (iy < 64) && (ix >= 0) && (ix < 64);
        const float* Ap = ok
            ? &g_img[((bi << 12) + (iy << 6) + ix) * DMODEL + ac]
            : (const float*)0;
        const float* Bp = Bbase + tap * DMODEL * DMODEL;
#pragma unroll 1
        for (int k0 = 0; k0 < DMODEL; k0 += 8) {
            float4 av = ok ? *(const float4*)(Ap + k0)
                           : make_float4(0.f, 0.f, 0.f, 0.f);
            float4 bv = *(const float4*)(Bp + k0 * DMODEL);
            __syncthreads();
            As[ac][arow]     = av.x;
            As[ac + 1][arow] = av.y;
            As[ac + 2][arow] = av.z;
            As[ac + 3][arow] = av.w;
            *(float4*)&Bs[brow][bcol] = bv;
            __syncthreads();
#pragma unroll
            for (int kk = 0; kk < 8; ++kk) {
                float4 a0 = *(const float4*)&As[kk][ty * 8];
                float4 a1 = *(const float4*)&As[kk][ty * 8 + 4];
                float4 b0 = *(const float4*)&Bs[kk][tx * 8];
                float4 b1 = *(const float4*)&Bs[kk][tx * 8 + 4];
                float a[8] = {a0.x, a0.y, a0.z, a0.w, a1.x, a1.y, a1.z, a1.w};
                float bb[8] = {b0.x, b0.y, b0.z, b0.w, b1.x, b1.y, b1.z, b1.w};
#pragma unroll
                for (int i = 0; i < 8; i++)
#pragma unroll
                    for (int j = 0; j < 8; j++) acc[i][j] += a[i] * bb[j];
            }
        }
    }
#pragma unroll
    for (int i = 0; i < 8; i++) {
        int mm = bm + ty * 8 + i;
        int bi2 = mm >> 12;
        int pix2 = mm & (IMG_N - 1);
        int orow = (bi2 * L_SEQ + HEAD_ROWS + pix2) * DMODEL;
        int c0 = bn + tx * 8;
#pragma unroll
        for (int j = 0; j < 8; j++) {
            int c = c0 + j;
            out[orow + c] = acc[i][j] + bias2[c] + x[orow + c];
        }
    }
}

// ---------------- launch ----------------
extern "C" void kernel_launch(void* const* d_in, const int* in_sizes, int n_in,
                              void* d_out, int out_size) {
    const float* x         = (const float*)d_in[0];
    const float* ln1_w     = (const float*)d_in[1];
    const float* ln1_b     = (const float*)d_in[2];
    const float* in_proj_w = (const float*)d_in[3];
    const float* conv1d_w  = (const float*)d_in[4];
    const float* conv1d_b  = (const float*)d_in[5];
    const float* dt_bias   = (const float*)d_in[6];
    const float* A_log     = (const float*)d_in[7];
    const float* Dskip     = (const float*)d_in[8];
    const float* norm_w    = (const float*)d_in[9];
    const float* out_proj_w= (const float*)d_in[10];
    const float* ln2_w     = (const float*)d_in[11];
    const float* ln2_b     = (const float*)d_in[12];
    const float* conv2d_w  = (const float*)d_in[13];
    const float* conv2d_b  = (const float*)d_in[14];
    float* out = (float*)d_out;

    void *pu, *pzx, *py_, *ph;
    cudaGetSymbolAddress(&pu, g_u);
    cudaGetSymbolAddress(&pzx, g_zx);
    cudaGetSymbolAddress(&py_, g_y);
    cudaGetSymbolAddress(&ph, g_h);

    // independent of pipeline: conv2d weight transpose
    wtrans_kernel<<<K_CONV, 256>>>(conv2d_w);

    ln1_kernel<<<ROWS, 256>>>(x, ln1_w, ln1_b);

    sgemm_kernel<<<dim3((DPROJ + 127) / 128, ROWS / 128), 256>>>(
        (const float*)pu, in_proj_w, (float*)pzx, ROWS, DPROJ, DMODEL);

    conv1d_kernel<<<ROWS, 256>>>(conv1d_w, conv1d_b);
    dtda_kernel<<<(ROWS * NHEADS + 255) / 256, 256>>>(dt_bias, A_log);

    scan_kernel<<<dim3(2, NHEADS, B_SZ), 1024>>>(Dskip);

    gate_rms_kernel<<<ROWS, 256>>>(norm_w);

    sgemm_kernel<<<dim3(DMODEL / 128, ROWS / 128), 256>>>(
        (const float*)py_, out_proj_w, (float*)ph, ROWS, DMODEL, DINNER);

    head_add_kernel<<<B_SZ * HEAD_ROWS, 256>>>(x, out);
    ln2_kernel<<<B_SZ * IMG_N, 256>>>(ln2_w, ln2_b);

    conv2d_gemm_kernel<<<dim3(DMODEL / 128, (B_SZ * IMG_N) / 128), 256>>>(
        x, conv2d_b, out);
}

// round 3
// speedup vs baseline: 1.7462x; 1.7462x over previous
#include <cuda_runtime.h>
#include <math.h>
#include <stdint.h>

#define B_SZ 2
#define L_SEQ 4352
#define DMODEL 768
#define DINNER 1536
#define DSTATE 128
#define NHEADS 24
#define HEADDIM 64
#define CONVDIM 1792
#define DPROJ 3352
#define IMG_N 4096
#define ROWS (B_SZ * L_SEQ)            // 8704
#define HEAD_ROWS (L_SEQ - IMG_N)      // 256
#define LN_EPS 1e-5f
#define K_CONV (25 * DMODEL)           // 19200

// ---------------- static scratch (no allocations allowed) ----------------
__device__ __align__(16) float g_u[ROWS * DMODEL];        // ln1 output
__device__ __align__(16) float g_zx[ROWS * DPROJ];        // in_proj output
__device__ __align__(16) float g_xbc[ROWS * CONVDIM];     // conv1d+silu output
__device__ float g_dt[ROWS * NHEADS];
__device__ float g_dA[ROWS * NHEADS];
__device__ __align__(16) float g_y[ROWS * DINNER];        // scan out / gated+normed
__device__ __align__(16) float g_h[ROWS * DMODEL];        // mamba block output
__device__ __align__(16) float g_img[B_SZ * IMG_N * DMODEL]; // ln2 output
__device__ __align__(16) float g_w2t[K_CONV * DMODEL];    // transposed conv2d weights

// ---------------- helpers ----------------
__device__ __forceinline__ float blockSum256(float v) {
    __shared__ float sh[8];
    __syncthreads();
#pragma unroll
    for (int o = 16; o; o >>= 1) v += __shfl_xor_sync(0xffffffffu, v, o);
    if ((threadIdx.x & 31) == 0) sh[threadIdx.x >> 5] = v;
    __syncthreads();
    float tot = 0.f;
#pragma unroll
    for (int i = 0; i < 8; i++) tot += sh[i];
    return tot;
}

__device__ __forceinline__ uint32_t f2tf32(float x) {
    uint32_t r;
    asm("cvt.rna.tf32.f32 %0, %1;" : "=r"(r) : "f"(x));
    return r;
}

__device__ __forceinline__ void mma8(float* c, const uint32_t* a, const uint32_t* b) {
    asm("mma.sync.aligned.m16n8k8.row.col.f32.tf32.tf32.f32 "
        "{%0,%1,%2,%3},{%4,%5,%6,%7},{%8,%9},{%0,%1,%2,%3};"
        : "+f"(c[0]), "+f"(c[1]), "+f"(c[2]), "+f"(c[3])
        : "r"(a[0]), "r"(a[1]), "r"(a[2]), "r"(a[3]), "r"(b[0]), "r"(b[1]));
}

// ---------------- LayerNorm 1 (x -> g_u) ----------------
__global__ void ln1_kernel(const float* __restrict__ x, const float* __restrict__ w,
                           const float* __restrict__ b) {
    int row = blockIdx.x;
    int tid = threadIdx.x;
    const float* xr = x + row * DMODEL;
    float v0 = xr[tid], v1 = xr[tid + 256], v2 = xr[tid + 512];
    float mean = blockSum256(v0 + v1 + v2) * (1.f / 768.f);
    float d0 = v0 - mean, d1 = v1 - mean, d2 = v2 - mean;
    float var = blockSum256(d0 * d0 + d1 * d1 + d2 * d2) * (1.f / 768.f);
    float rs = rsqrtf(var + LN_EPS);
    float* o = g_u + row * DMODEL;
    o[tid]       = d0 * rs * w[tid]       + b[tid];
    o[tid + 256] = d1 * rs * w[tid + 256] + b[tid + 256];
    o[tid + 512] = d2 * rs * w[tid + 512] + b[tid + 512];
}

// ---------------- LayerNorm 2 (g_h tail -> g_img) ----------------
__global__ void ln2_kernel(const float* __restrict__ w, const float* __restrict__ b) {
    int m = blockIdx.x;
    int tid = threadIdx.x;
    int bb = m >> 12, pix = m & (IMG_N - 1);
    const float* xr = g_h + (bb * L_SEQ + HEAD_ROWS + pix) * DMODEL;
    float v0 = xr[tid], v1 = xr[tid + 256], v2 = xr[tid + 512];
    float mean = blockSum256(v0 + v1 + v2) * (1.f / 768.f);
    float d0 = v0 - mean, d1 = v1 - mean, d2 = v2 - mean;
    float var = blockSum256(d0 * d0 + d1 * d1 + d2 * d2) * (1.f / 768.f);
    float rs = rsqrtf(var + LN_EPS);
    float* o = g_img + m * DMODEL;
    o[tid]       = d0 * rs * w[tid]       + b[tid];
    o[tid + 256] = d1 * rs * w[tid + 256] + b[tid + 256];
    o[tid + 512] = d2 * rs * w[tid + 512] + b[tid + 512];
}

// ---------------- fp32 tiled SGEMM (kept for in_proj; ragged N) ----------------
__global__ __launch_bounds__(256) void sgemm_kernel(
    const float* __restrict__ A, const float* __restrict__ Bm,
    float* __restrict__ C, int M, int N, int K) {
    __shared__ __align__(16) float As[8][132];
    __shared__ __align__(16) float Bs[8][128];
    int tid = threadIdx.x;
    int bm = blockIdx.y * 128, bn = blockIdx.x * 128;
    int arow = tid >> 1, ac = (tid & 1) << 2;
    int brow = tid >> 5, bcol = (tid & 31) << 2;
    int ty = tid >> 4, tx = tid & 15;
    float acc[8][8];
#pragma unroll
    for (int i = 0; i < 8; i++)
#pragma unroll
        for (int j = 0; j < 8; j++) acc[i][j] = 0.f;
    const float* Ap = A + (bm + arow) * K + ac;
    bool nfull = (bn + 128 <= N);
    int col = bn + bcol;
    for (int k0 = 0; k0 < K; k0 += 8) {
        float4 av = *(const float4*)(Ap + k0);
        float4 bv = make_float4(0.f, 0.f, 0.f, 0.f);
        const float* Bp = Bm + (k0 + brow) * N;
        if (nfull || col + 3 < N) {
            bv = *(const float4*)(Bp + col);
        } else {
            if (col     < N) bv.x = Bp[col];
            if (col + 1 < N) bv.y = Bp[col + 1];
            if (col + 2 < N) bv.z = Bp[col + 2];
        }
        __syncthreads();
        As[ac][arow]     = av.x;
        As[ac + 1][arow] = av.y;
        As[ac + 2][arow] = av.z;
        As[ac + 3][arow] = av.w;
        *(float4*)&Bs[brow][bcol] = bv;
        __syncthreads();
#pragma unroll
        for (int kk = 0; kk < 8; ++kk) {
            float4 a0 = *(const float4*)&As[kk][ty * 8];
            float4 a1 = *(const float4*)&As[kk][ty * 8 + 4];
            float4 b0 = *(const float4*)&Bs[kk][tx * 8];
            float4 b1 = *(const float4*)&Bs[kk][tx * 8 + 4];
            float a[8] = {a0.x, a0.y, a0.z, a0.w, a1.x, a1.y, a1.z, a1.w};
            float bb[8] = {b0.x, b0.y, b0.z, b0.w, b1.x, b1.y, b1.z, b1.w};
#pragma unroll
            for (int i = 0; i < 8; i++)
#pragma unroll
                for (int j = 0; j < 8; j++) acc[i][j] += a[i] * bb[j];
        }
    }
#pragma unroll
    for (int i = 0; i < 8; i++) {
        int m = bm + ty * 8 + i;
        float* Cr = C + m * N;
        int c0 = bn + tx * 8;
        if (nfull || c0 + 7 < N) {
            float4 v0 = {acc[i][0], acc[i][1], acc[i][2], acc[i][3]};
            float4 v1 = {acc[i][4], acc[i][5], acc[i][6], acc[i][7]};
            *(float4*)(Cr + c0) = v0;
            *(float4*)(Cr + c0 + 4) = v1;
        } else {
            for (int j = 0; j < 8; j++)
                if (c0 + j < N) Cr[c0 + j] = acc[i][j];
        }
    }
}

// ============================================================================
// TF32 tensor-core GEMM core: 128x128 block tile, BK=16, 8 warps (2x4),
// warp tile 64x32, mma.m16n8k8. A smem [m][k] stride 20 (conflict-free frag
// loads: 20 ≡ 4 mod 32), B smem [k][n] stride 136 (≡ 8 mod 32, conflict-free).
// ============================================================================

// plain C[M,N] = A[M,K] @ B[K,N], M%128==0, N%128==0, K%16==0
__global__ __launch_bounds__(256) void sgemm_mma_kernel(
    const float* __restrict__ A, const float* __restrict__ Bm,
    float* __restrict__ C, int M, int N, int K) {
    __shared__ uint32_t As[128 * 20];
    __shared__ uint32_t Bs[16 * 136];
    int tid = threadIdx.x;
    int bm = blockIdx.y * 128, bn = blockIdx.x * 128;
    int arow = tid >> 1, acol = (tid & 1) << 3;      // 2 thr/row, 8 cols each
    int brow = tid >> 4, bcol = (tid & 15) << 3;     // 16 rows, 8 cols each
    int lane = tid & 31, w = tid >> 5;
    int wm = w >> 2, wn = w & 3;                     // 2 x 4 warps
    int gid = lane >> 2, tig = lane & 3;

    float acc[4][4][4];
#pragma unroll
    for (int i = 0; i < 4; i++)
#pragma unroll
        for (int j = 0; j < 4; j++)
#pragma unroll
            for (int q = 0; q < 4; q++) acc[i][j][q] = 0.f;

    const float* Ap = A + (bm + arow) * K + acol;
    const float* Bp0 = Bm + bn + bcol;

    for (int k0 = 0; k0 < K; k0 += 16) {
        float4 av0 = *(const float4*)(Ap + k0);
        float4 av1 = *(const float4*)(Ap + k0 + 4);
        const float* Bp = Bp0 + (k0 + brow) * N;
        float4 bv0 = *(const float4*)(Bp);
        float4 bv1 = *(const float4*)(Bp + 4);
        __syncthreads();
        uint32_t* as = &As[arow * 20 + acol];
        as[0] = f2tf32(av0.x); as[1] = f2tf32(av0.y);
        as[2] = f2tf32(av0.z); as[3] = f2tf32(av0.w);
        as[4] = f2tf32(av1.x); as[5] = f2tf32(av1.y);
        as[6] = f2tf32(av1.z); as[7] = f2tf32(av1.w);
        uint32_t* bs = &Bs[brow * 136 + bcol];
        bs[0] = f2tf32(bv0.x); bs[1] = f2tf32(bv0.y);
        bs[2] = f2tf32(bv0.z); bs[3] = f2tf32(bv0.w);
        bs[4] = f2tf32(bv1.x); bs[5] = f2tf32(bv1.y);
        bs[6] = f2tf32(bv1.z); bs[7] = f2tf32(bv1.w);
        __syncthreads();
#pragma unroll
        for (int ks = 0; ks < 2; ++ks) {
            int k8 = ks * 8;
            uint32_t af[4][4], bf[4][2];
#pragma unroll
            for (int tm = 0; tm < 4; tm++) {
                int r0 = wm * 64 + tm * 16 + gid;
                af[tm][0] = As[r0 * 20 + k8 + tig];
                af[tm][1] = As[(r0 + 8) * 20 + k8 + tig];
                af[tm][2] = As[r0 * 20 + k8 + tig + 4];
                af[tm][3] = As[(r0 + 8) * 20 + k8 + tig + 4];
            }
#pragma unroll
            for (int tn = 0; tn < 4; tn++) {
                int cl = wn * 32 + tn * 8 + gid;
                bf[tn][0] = Bs[(k8 + tig) * 136 + cl];
                bf[tn][1] = Bs[(k8 + tig + 4) * 136 + cl];
            }
#pragma unroll
            for (int tm = 0; tm < 4; tm++)
#pragma unroll
                for (int tn = 0; tn < 4; tn++)
                    mma8(acc[tm][tn], af[tm], bf[tn]);
        }
    }
    // epilogue: plain store
#pragma unroll
    for (int tm = 0; tm < 4; tm++) {
        int r0 = bm + wm * 64 + tm * 16 + gid;
#pragma unroll
        for (int tn = 0; tn < 4; tn++) {
            int c = bn + wn * 32 + tn * 8 + tig * 2;
            *(float2*)&C[r0 * N + c]       = make_float2(acc[tm][tn][0], acc[tm][tn][1]);
            *(float2*)&C[(r0 + 8) * N + c] = make_float2(acc[tm][tn][2], acc[tm][tn][3]);
        }
    }
}

// conv2d 5x5 SAME implicit GEMM on tensor cores + bias + residual.
// M = 8192, N = 768, K = 25 taps x 768. Writes tail rows of d_out.
__global__ __launch_bounds__(256) void conv2d_mma_kernel(
    const float* __restrict__ x, const float* __restrict__ bias2,
    float* __restrict__ out) {
    __shared__ uint32_t As[128 * 20];
    __shared__ uint32_t Bs[16 * 136];
    int tid = threadIdx.x;
    int bm = blockIdx.y * 128, bn = blockIdx.x * 128;
    int arow = tid >> 1, acol = (tid & 1) << 3;
    int brow = tid >> 4, bcol = (tid & 15) << 3;
    int lane = tid & 31, w = tid >> 5;
    int wm = w >> 2, wn = w & 3;
    int gid = lane >> 2, tig = lane & 3;

    float acc[4][4][4];
#pragma unroll
    for (int i = 0; i < 4; i++)
#pragma unroll
        for (int j = 0; j < 4; j++)
#pragma unroll
            for (int q = 0; q < 4; q++) acc[i][j][q] = 0.f;

    int m = bm + arow;
    int bi = m >> 12;
    int pix = m & (IMG_N - 1);
    int py = pix >> 6, px = pix & 63;

    for (int tap = 0; tap < 25; ++tap) {
        int ky = tap / 5, kx = tap - ky * 5;
        int iy = py + ky - 2, ix = px + kx - 2;
        bool ok = (iy >= 0) && (iy < 64) && (ix >= 0) && (ix < 64);
        const float* Ap = ok
            ? &g_img[((bi << 12) + (iy << 6) + ix) * DMODEL + acol]
            : (const float*)0;
        const float* Bp0 = g_w2t + (tap * DMODEL + brow) * DMODEL + bn + bcol;
#pragma unroll 1
        for (int k0 = 0; k0 < DMODEL; k0 += 16) {
            float4 av0 = make_float4(0.f, 0.f, 0.f, 0.f);
            float4 av1 = make_float4(0.f, 0.f, 0.f, 0.f);
            if (ok) {
                av0 = *(const float4*)(Ap + k0);
                av1 = *(const float4*)(Ap + k0 + 4);
            }
            const float* Bp = Bp0 + k0 * DMODEL;
            float4 bv0 = *(const float4*)(Bp);
            float4 bv1 = *(const float4*)(Bp + 4);
            __syncthreads();
            uint32_t* as = &As[arow * 20 + acol];
            as[0] = f2tf32(av0.x); as[1] = f2tf32(av0.y);
            as[2] = f2tf32(av0.z); as[3] = f2tf32(av0.w);
            as[4] = f2tf32(av1.x); as[5] = f2tf32(av1.y);
            as[6] = f2tf32(av1.z); as[7] = f2tf32(av1.w);
            uint32_t* bs = &Bs[brow * 136 + bcol];
            bs[0] = f2tf32(bv0.x); bs[1] = f2tf32(bv0.y);
            bs[2] = f2tf32(bv0.z); bs[3] = f2tf32(bv0.w);
            bs[4] = f2tf32(bv1.x); bs[5] = f2tf32(bv1.y);
            bs[6] = f2tf32(bv1.z); bs[7] = f2tf32(bv1.w);
            __syncthreads();
#pragma unroll
            for (int ks = 0; ks < 2; ++ks) {
                int k8 = ks * 8;
                uint32_t af[4][4], bf[4][2];
#pragma unroll
                for (int tm = 0; tm < 4; tm++) {
                    int r0 = wm * 64 + tm * 16 + gid;
                    af[tm][0] = As[r0 * 20 + k8 + tig];
                    af[tm][1] = As[(r0 + 8) * 20 + k8 + tig];
                    af[tm][2] = As[r0 * 20 + k8 + tig + 4];
                    af[tm][3] = As[(r0 + 8) * 20 + k8 + tig + 4];
                }
#pragma unroll
                for (int tn = 0; tn < 4; tn++) {
                    int cl = wn * 32 + tn * 8 + gid;
                    bf[tn][0] = Bs[(k8 + tig) * 136 + cl];
                    bf[tn][1] = Bs[(k8 + tig + 4) * 136 + cl];
                }
#pragma unroll
                for (int tm = 0; tm < 4; tm++)
#pragma unroll
                    for (int tn = 0; tn < 4; tn++)
                        mma8(acc[tm][tn], af[tm], bf[tn]);
            }
        }
    }
    // epilogue: out = acc + bias + residual, remapped rows
#pragma unroll
    for (int tm = 0; tm < 4; tm++) {
        int mm0 = bm + wm * 64 + tm * 16 + gid;
        int mm1 = mm0 + 8;
        int orow0 = (((mm0 >> 12) * L_SEQ) + HEAD_ROWS + (mm0 & (IMG_N - 1))) * DMODEL;
        int orow1 = (((mm1 >> 12) * L_SEQ) + HEAD_ROWS + (mm1 & (IMG_N - 1))) * DMODEL;
#pragma unroll
        for (int tn = 0; tn < 4; tn++) {
            int c = bn + wn * 32 + tn * 8 + tig * 2;
            float2 bsv = *(const float2*)&bias2[c];
            float2 x0 = *(const float2*)&x[orow0 + c];
            float2 x1 = *(const float2*)&x[orow1 + c];
            *(float2*)&out[orow0 + c] = make_float2(
                acc[tm][tn][0] + bsv.x + x0.x, acc[tm][tn][1] + bsv.y + x0.y);
            *(float2*)&out[orow1 + c] = make_float2(
                acc[tm][tn][2] + bsv.x + x1.x, acc[tm][tn][3] + bsv.y + x1.y);
        }
    }
}

// ---------------- depthwise causal conv1d + silu ----------------
__global__ void conv1d_kernel(const float* __restrict__ w, const float* __restrict__ bias) {
    int row = blockIdx.x;
    int b = row / L_SEQ;
    int l = row - b * L_SEQ;
    for (int c = threadIdx.x; c < CONVDIM; c += 256) {
        float acc = bias[c];
#pragma unroll
        for (int j = 0; j < 4; j++) {
            int ll = l - 3 + j;
            if (ll >= 0)
                acc += g_zx[(b * L_SEQ + ll) * DPROJ + DINNER + c] * w[c * 4 + j];
        }
        acc = acc / (1.f + expf(-acc));  // silu
        g_xbc[row * CONVDIM + c] = acc;
    }
}

// ---------------- dt = softplus(raw + bias), dA = exp(dt * -exp(A_log)) ----------------
__global__ void dtda_kernel(const float* __restrict__ dt_bias, const float* __restrict__ A_log) {
    int i = blockIdx.x * 256 + threadIdx.x;
    if (i >= ROWS * NHEADS) return;
    int row = i / NHEADS;
    int h = i - row * NHEADS;
    float v = g_zx[row * DPROJ + (DINNER + CONVDIM) + h] + dt_bias[h];
    float dtv = (v > 20.f) ? v : log1pf(expf(v));
    g_dt[i] = dtv;
    g_dA[i] = expf(-dtv * expf(A_log[h]));
}

// ---------------- selective scan ----------------
__global__ __launch_bounds__(1024) void scan_kernel(const float* __restrict__ Dskip) {
    int warp = threadIdx.x >> 5, lane = threadIdx.x & 31;
    int p = blockIdx.x * 32 + warp;
    int hh = blockIdx.y, b = blockIdx.z;
    int ch = hh * HEADDIM + p;
    float h0 = 0.f, h1 = 0.f, h2 = 0.f, h3 = 0.f;
    float Dh = Dskip[hh];
    int nb = lane * 4;
    for (int t = 0; t < L_SEQ; ++t) {
        int r = b * L_SEQ + t;
        int base = r * CONVDIM;
        float dAt = g_dA[r * NHEADS + hh];
        float dtt = g_dt[r * NHEADS + hh];
        float xs = g_xbc[base + ch];
        float dtx = dtt * xs;
        float4 Bv = *(const float4*)&g_xbc[base + DINNER + nb];
        float4 Cv = *(const float4*)&g_xbc[base + DINNER + DSTATE + nb];
        h0 = h0 * dAt + dtx * Bv.x;
        h1 = h1 * dAt + dtx * Bv.y;
        h2 = h2 * dAt + dtx * Bv.z;
        h3 = h3 * dAt + dtx * Bv.w;
        float part = h0 * Cv.x + h1 * Cv.y + h2 * Cv.z + h3 * Cv.w;
#pragma unroll
        for (int o = 16; o; o >>= 1) part += __shfl_xor_sync(0xffffffffu, part, o);
        if (lane == 0) g_y[r * DINNER + ch] = part + Dh * xs;
    }
}

// ---------------- y = y * silu(z); RMSNorm; * norm_w ----------------
__global__ void gate_rms_kernel(const float* __restrict__ norm_w) {
    int row = blockIdx.x;
    int tid = threadIdx.x;
    __shared__ float sh[DINNER];
    float ss = 0.f;
#pragma unroll
    for (int it = 0; it < 6; ++it) {
        int c = tid + it * 256;
        float z = g_zx[row * DPROJ + c];
        float yv = g_y[row * DINNER + c];
        float t = yv * (z / (1.f + expf(-z)));
        sh[c] = t;
        ss += t * t;
    }
    float tot = blockSum256(ss);
    float sc = rsqrtf(tot * (1.f / 1536.f) + LN_EPS);
#pragma unroll
    for (int it = 0; it < 6; ++it) {
        int c = tid + it * 256;
        g_y[row * DINNER + c] = sh[c] * sc * norm_w[c];
    }
}

// ---------------- head rows: out = x + h ----------------
__global__ void head_add_kernel(const float* __restrict__ x, float* __restrict__ out) {
    int row = blockIdx.x;
    int b = row / HEAD_ROWS;
    int l = row - b * HEAD_ROWS;
    int g = (b * L_SEQ + l) * DMODEL;
    for (int c = threadIdx.x; c < DMODEL; c += 256)
        out[g + c] = x[g + c] + g_h[g + c];
}

// ---------------- conv2d weight transpose: w2t[tap*768+ci][co] ----------------
__global__ void wtrans_kernel(const float* __restrict__ w2) {
    int k = blockIdx.x;
    int tap = k / DMODEL;
    int ci = k - tap * DMODEL;
    const float* src = w2 + ci * 25 + tap;
    float* dst = g_w2t + k * DMODEL;
    for (int n = threadIdx.x; n < DMODEL; n += 256)
        dst[n] = src[n * K_CONV];
}

// ---------------- launch ----------------
extern "C" void kernel_launch(void* const* d_in, const int* in_sizes, int n_in,
                              void* d_out, int out_size) {
    const float* x         = (const float*)d_in[0];
    const float* ln1_w     = (const float*)d_in[1];
    const float* ln1_b     = (const float*)d_in[2];
    const float* in_proj_w = (const float*)d_in[3];
    const float* conv1d_w  = (const float*)d_in[4];
    const float* conv1d_b  = (const float*)d_in[5];
    const float* dt_bias   = (const float*)d_in[6];
    const float* A_log     = (const float*)d_in[7];
    const float* Dskip     = (const float*)d_in[8];
    const float* norm_w    = (const float*)d_in[9];
    const float* out_proj_w= (const float*)d_in[10];
    const float* ln2_w     = (const float*)d_in[11];
    const float* ln2_b     = (const float*)d_in[12];
    const float* conv2d_w  = (const float*)d_in[13];
    const float* conv2d_b  = (const float*)d_in[14];
    float* out = (float*)d_out;

    void *pu, *pzx, *py_, *ph;
    cudaGetSymbolAddress(&pu, g_u);
    cudaGetSymbolAddress(&pzx, g_zx);
    cudaGetSymbolAddress(&py_, g_y);
    cudaGetSymbolAddress(&ph, g_h);

    wtrans_kernel<<<K_CONV, 256>>>(conv2d_w);

    ln1_kernel<<<ROWS, 256>>>(x, ln1_w, ln1_b);

    sgemm_kernel<<<dim3((DPROJ + 127) / 128, ROWS / 128), 256>>>(
        (const float*)pu, in_proj_w, (float*)pzx, ROWS, DPROJ, DMODEL);

    conv1d_kernel<<<ROWS, 256>>>(conv1d_w, conv1d_b);
    dtda_kernel<<<(ROWS * NHEADS + 255) / 256, 256>>>(dt_bias, A_log);

    scan_kernel<<<dim3(2, NHEADS, B_SZ), 1024>>>(Dskip);

    gate_rms_kernel<<<ROWS, 256>>>(norm_w);

    sgemm_mma_kernel<<<dim3(DMODEL / 128, ROWS / 128), 256>>>(
        (const float*)py_, out_proj_w, (float*)ph, ROWS, DMODEL, DINNER);

    head_add_kernel<<<B_SZ * HEAD_ROWS, 256>>>(x, out);
    ln2_kernel<<<B_SZ * IMG_N, 256>>>(ln2_w, ln2_b);

    conv2d_mma_kernel<<<dim3(DMODEL / 128, (B_SZ * IMG_N) / 128), 256>>>(
        x, conv2d_b, out);
}

// round 4
// speedup vs baseline: 2.2581x; 1.2932x over previous
#include <cuda_runtime.h>
#include <math.h>
#include <stdint.h>

#define B_SZ 2
#define L_SEQ 4352
#define DMODEL 768
#define DINNER 1536
#define DSTATE 128
#define NHEADS 24
#define HEADDIM 64
#define CONVDIM 1792
#define DPROJ 3352
#define IMG_N 4096
#define ROWS (B_SZ * L_SEQ)            // 8704
#define HEAD_ROWS (L_SEQ - IMG_N)      // 256
#define LN_EPS 1e-5f
#define K_CONV (25 * DMODEL)           // 19200

// ---------------- static scratch (no allocations allowed) ----------------
__device__ __align__(16) float g_u[ROWS * DMODEL];        // ln1 output
__device__ __align__(16) float g_zx[ROWS * DPROJ];        // in_proj output
__device__ __align__(16) float g_xbc[ROWS * CONVDIM];     // conv1d+silu output
__device__ float g_dt[ROWS * NHEADS];
__device__ float g_dA[ROWS * NHEADS];
__device__ __align__(16) float g_y[ROWS * DINNER];        // scan out / gated+normed
__device__ __align__(16) float g_h[ROWS * DMODEL];        // mamba block output
__device__ __align__(16) float g_img[B_SZ * IMG_N * DMODEL]; // ln2 output
__device__ __align__(16) float g_w2t[K_CONV * DMODEL];    // transposed conv2d weights

// ---------------- helpers ----------------
__device__ __forceinline__ float blockSum256(float v) {
    __shared__ float sh[8];
    __syncthreads();
#pragma unroll
    for (int o = 16; o; o >>= 1) v += __shfl_xor_sync(0xffffffffu, v, o);
    if ((threadIdx.x & 31) == 0) sh[threadIdx.x >> 5] = v;
    __syncthreads();
    float tot = 0.f;
#pragma unroll
    for (int i = 0; i < 8; i++) tot += sh[i];
    return tot;
}

__device__ __forceinline__ uint32_t f2tf32(float x) {
    uint32_t r;
    asm("cvt.rna.tf32.f32 %0, %1;" : "=r"(r) : "f"(x));
    return r;
}

__device__ __forceinline__ void mma8(float* c, const uint32_t* a, const uint32_t* b) {
    asm("mma.sync.aligned.m16n8k8.row.col.f32.tf32.tf32.f32 "
        "{%0,%1,%2,%3},{%4,%5,%6,%7},{%8,%9},{%0,%1,%2,%3};"
        : "+f"(c[0]), "+f"(c[1]), "+f"(c[2]), "+f"(c[3])
        : "r"(a[0]), "r"(a[1]), "r"(a[2]), "r"(a[3]), "r"(b[0]), "r"(b[1]));
}

// ---------------- LayerNorm 1 (x -> g_u) ----------------
__global__ void ln1_kernel(const float* __restrict__ x, const float* __restrict__ w,
                           const float* __restrict__ b) {
    int row = blockIdx.x;
    int tid = threadIdx.x;
    const float* xr = x + row * DMODEL;
    float v0 = xr[tid], v1 = xr[tid + 256], v2 = xr[tid + 512];
    float mean = blockSum256(v0 + v1 + v2) * (1.f / 768.f);
    float d0 = v0 - mean, d1 = v1 - mean, d2 = v2 - mean;
    float var = blockSum256(d0 * d0 + d1 * d1 + d2 * d2) * (1.f / 768.f);
    float rs = rsqrtf(var + LN_EPS);
    float* o = g_u + row * DMODEL;
    o[tid]       = d0 * rs * w[tid]       + b[tid];
    o[tid + 256] = d1 * rs * w[tid + 256] + b[tid + 256];
    o[tid + 512] = d2 * rs * w[tid + 512] + b[tid + 512];
}

// ---------------- LayerNorm 2 (g_h tail -> g_img) ----------------
__global__ void ln2_kernel(const float* __restrict__ w, const float* __restrict__ b) {
    int m = blockIdx.x;
    int tid = threadIdx.x;
    int bb = m >> 12, pix = m & (IMG_N - 1);
    const float* xr = g_h + (bb * L_SEQ + HEAD_ROWS + pix) * DMODEL;
    float v0 = xr[tid], v1 = xr[tid + 256], v2 = xr[tid + 512];
    float mean = blockSum256(v0 + v1 + v2) * (1.f / 768.f);
    float d0 = v0 - mean, d1 = v1 - mean, d2 = v2 - mean;
    float var = blockSum256(d0 * d0 + d1 * d1 + d2 * d2) * (1.f / 768.f);
    float rs = rsqrtf(var + LN_EPS);
    float* o = g_img + m * DMODEL;
    o[tid]       = d0 * rs * w[tid]       + b[tid];
    o[tid + 256] = d1 * rs * w[tid + 256] + b[tid + 256];
    o[tid + 512] = d2 * rs * w[tid + 512] + b[tid + 512];
}

// ============================================================================
// TF32 tensor-core GEMM, double-buffered smem, one sync per k-tile.
// 128x128 block tile, BK=16, 8 warps (2x4), warp tile 64x32, mma.m16n8k8.
// A smem stride 20 (conflict-free), B smem stride 136 (conflict-free).
// Ragged N supported when N % 8 == 0 (8-aligned all-or-nothing guards).
// ============================================================================
__global__ __launch_bounds__(256) void sgemm_mma_kernel(
    const float* __restrict__ A, const float* __restrict__ Bm,
    float* __restrict__ C, int M, int N, int K) {
    __shared__ uint32_t As[2][128 * 20];
    __shared__ uint32_t Bs[2][16 * 136];
    int tid = threadIdx.x;
    int bm = blockIdx.y * 128, bn = blockIdx.x * 128;
    int arow = tid >> 1, acol = (tid & 1) << 3;
    int brow = tid >> 4, bcol = (tid & 15) << 3;
    int lane = tid & 31, w = tid >> 5;
    int wm = w >> 2, wn = w & 3;
    int gid = lane >> 2, tig = lane & 3;

    float acc[4][4][4];
#pragma unroll
    for (int i = 0; i < 4; i++)
#pragma unroll
        for (int j = 0; j < 4; j++)
#pragma unroll
            for (int q = 0; q < 4; q++) acc[i][j][q] = 0.f;

    const float* Ap = A + (bm + arow) * K + acol;
    int colb = bn + bcol;
    bool bok = (colb < N);            // N % 8 == 0 -> whole 8-wide load valid iff true
    const float* Bp0 = Bm + colb;

    float4 av0, av1, bv0, bv1;
    // preload k0 = 0
    av0 = *(const float4*)(Ap);
    av1 = *(const float4*)(Ap + 4);
    {
        const float* Bp = Bp0 + brow * N;
        if (bok) { bv0 = *(const float4*)(Bp); bv1 = *(const float4*)(Bp + 4); }
        else { bv0 = bv1 = make_float4(0.f, 0.f, 0.f, 0.f); }
    }

    int ntiles = K >> 4;
    for (int kt = 0; kt < ntiles; ++kt) {
        int buf = kt & 1;
        uint32_t* as = &As[buf][arow * 20 + acol];
        as[0] = f2tf32(av0.x); as[1] = f2tf32(av0.y);
        as[2] = f2tf32(av0.z); as[3] = f2tf32(av0.w);
        as[4] = f2tf32(av1.x); as[5] = f2tf32(av1.y);
        as[6] = f2tf32(av1.z); as[7] = f2tf32(av1.w);
        uint32_t* bs = &Bs[buf][brow * 136 + bcol];
        bs[0] = f2tf32(bv0.x); bs[1] = f2tf32(bv0.y);
        bs[2] = f2tf32(bv0.z); bs[3] = f2tf32(bv0.w);
        bs[4] = f2tf32(bv1.x); bs[5] = f2tf32(bv1.y);
        bs[6] = f2tf32(bv1.z); bs[7] = f2tf32(bv1.w);
        __syncthreads();
        if (kt + 1 < ntiles) {
            int k0 = (kt + 1) << 4;
            av0 = *(const float4*)(Ap + k0);
            av1 = *(const float4*)(Ap + k0 + 4);
            const float* Bp = Bp0 + (k0 + brow) * N;
            if (bok) { bv0 = *(const float4*)(Bp); bv1 = *(const float4*)(Bp + 4); }
            else { bv0 = bv1 = make_float4(0.f, 0.f, 0.f, 0.f); }
        }
        const uint32_t* Asb = As[buf];
        const uint32_t* Bsb = Bs[buf];
#pragma unroll
        for (int ks = 0; ks < 2; ++ks) {
            int k8 = ks * 8;
            uint32_t af[4][4], bf[4][2];
#pragma unroll
            for (int tm = 0; tm < 4; tm++) {
                int r0 = wm * 64 + tm * 16 + gid;
                af[tm][0] = Asb[r0 * 20 + k8 + tig];
                af[tm][1] = Asb[(r0 + 8) * 20 + k8 + tig];
                af[tm][2] = Asb[r0 * 20 + k8 + tig + 4];
                af[tm][3] = Asb[(r0 + 8) * 20 + k8 + tig + 4];
            }
#pragma unroll
            for (int tn = 0; tn < 4; tn++) {
                int cl = wn * 32 + tn * 8 + gid;
                bf[tn][0] = Bsb[(k8 + tig) * 136 + cl];
                bf[tn][1] = Bsb[(k8 + tig + 4) * 136 + cl];
            }
#pragma unroll
            for (int tm = 0; tm < 4; tm++)
#pragma unroll
                for (int tn = 0; tn < 4; tn++)
                    mma8(acc[tm][tn], af[tm], bf[tn]);
        }
    }
#pragma unroll
    for (int tm = 0; tm < 4; tm++) {
        int r0 = bm + wm * 64 + tm * 16 + gid;
#pragma unroll
        for (int tn = 0; tn < 4; tn++) {
            int c = bn + wn * 32 + tn * 8 + tig * 2;
            if (c < N) {
                *(float2*)&C[r0 * N + c]       = make_float2(acc[tm][tn][0], acc[tm][tn][1]);
                *(float2*)&C[(r0 + 8) * N + c] = make_float2(acc[tm][tn][2], acc[tm][tn][3]);
            }
        }
    }
}

// conv2d 5x5 SAME implicit GEMM on tensor cores + bias + residual.
// M = 8192, N = 768, K = 1200 tiles of 16 (25 taps x 48). Double-buffered.
__global__ __launch_bounds__(256) void conv2d_mma_kernel(
    const float* __restrict__ x, const float* __restrict__ bias2,
    float* __restrict__ out) {
    __shared__ uint32_t As[2][128 * 20];
    __shared__ uint32_t Bs[2][16 * 136];
    int tid = threadIdx.x;
    int bm = blockIdx.y * 128, bn = blockIdx.x * 128;
    int arow = tid >> 1, acol = (tid & 1) << 3;
    int brow = tid >> 4, bcol = (tid & 15) << 3;
    int lane = tid & 31, w = tid >> 5;
    int wm = w >> 2, wn = w & 3;
    int gid = lane >> 2, tig = lane & 3;

    float acc[4][4][4];
#pragma unroll
    for (int i = 0; i < 4; i++)
#pragma unroll
        for (int j = 0; j < 4; j++)
#pragma unroll
            for (int q = 0; q < 4; q++) acc[i][j][q] = 0.f;

    int m = bm + arow;
    int bi = m >> 12;
    int pix = m & (IMG_N - 1);
    int py = pix >> 6, px = pix & 63;

    // streaming tap state
    int ky = 0, kx = 0;
    int iy = py - 2, ix = px - 2;
    bool ok = (iy >= 0) && (iy < 64) && (ix >= 0) && (ix < 64);
    const float* Abase = &g_img[((bi << 12) + (iy << 6) + ix) * DMODEL + acol];
    int aoff = 0;
    const float* Bp = g_w2t + brow * DMODEL + bn + bcol;   // advances 16*768 per tile

    float4 av0, av1, bv0, bv1;
    if (ok) { av0 = *(const float4*)(Abase); av1 = *(const float4*)(Abase + 4); }
    else { av0 = av1 = make_float4(0.f, 0.f, 0.f, 0.f); }
    bv0 = *(const float4*)(Bp);
    bv1 = *(const float4*)(Bp + 4);

    const int NTILES = 25 * (DMODEL / 16);   // 1200
    for (int kt = 0; kt < NTILES; ++kt) {
        int buf = kt & 1;
        uint32_t* as = &As[buf][arow * 20 + acol];
        as[0] = f2tf32(av0.x); as[1] = f2tf32(av0.y);
        as[2] = f2tf32(av0.z); as[3] = f2tf32(av0.w);
        as[4] = f2tf32(av1.x); as[5] = f2tf32(av1.y);
        as[6] = f2tf32(av1.z); as[7] = f2tf32(av1.w);
        uint32_t* bs = &Bs[buf][brow * 136 + bcol];
        bs[0] = f2tf32(bv0.x); bs[1] = f2tf32(bv0.y);
        bs[2] = f2tf32(bv0.z); bs[3] = f2tf32(bv0.w);
        bs[4] = f2tf32(bv1.x); bs[5] = f2tf32(bv1.y);
        bs[6] = f2tf32(bv1.z); bs[7] = f2tf32(bv1.w);
        __syncthreads();
        if (kt + 1 < NTILES) {
            aoff += 16;
            if (aoff == DMODEL) {          // next tap
                aoff = 0;
                kx++;
                if (kx == 5) { kx = 0; ky++; }
                iy = py + ky - 2; ix = px + kx - 2;
                ok = (iy >= 0) && (iy < 64) && (ix >= 0) && (ix < 64);
                Abase = &g_img[((bi << 12) + (iy << 6) + ix) * DMODEL + acol];
            }
            if (ok) { av0 = *(const float4*)(Abase + aoff); av1 = *(const float4*)(Abase + aoff + 4); }
            else { av0 = av1 = make_float4(0.f, 0.f, 0.f, 0.f); }
            Bp += 16 * DMODEL;
            bv0 = *(const float4*)(Bp);
            bv1 = *(const float4*)(Bp + 4);
        }
        const uint32_t* Asb = As[buf];
        const uint32_t* Bsb = Bs[buf];
#pragma unroll
        for (int ks = 0; ks < 2; ++ks) {
            int k8 = ks * 8;
            uint32_t af[4][4], bf[4][2];
#pragma unroll
            for (int tm = 0; tm < 4; tm++) {
                int r0 = wm * 64 + tm * 16 + gid;
                af[tm][0] = Asb[r0 * 20 + k8 + tig];
                af[tm][1] = Asb[(r0 + 8) * 20 + k8 + tig];
                af[tm][2] = Asb[r0 * 20 + k8 + tig + 4];
                af[tm][3] = Asb[(r0 + 8) * 20 + k8 + tig + 4];
            }
#pragma unroll
            for (int tn = 0; tn < 4; tn++) {
                int cl = wn * 32 + tn * 8 + gid;
                bf[tn][0] = Bsb[(k8 + tig) * 136 + cl];
                bf[tn][1] = Bsb[(k8 + tig + 4) * 136 + cl];
            }
#pragma unroll
            for (int tm = 0; tm < 4; tm++)
#pragma unroll
                for (int tn = 0; tn < 4; tn++)
                    mma8(acc[tm][tn], af[tm], bf[tn]);
        }
    }
    // epilogue: out = acc + bias + residual, remapped rows
#pragma unroll
    for (int tm = 0; tm < 4; tm++) {
        int mm0 = bm + wm * 64 + tm * 16 + gid;
        int mm1 = mm0 + 8;
        int orow0 = (((mm0 >> 12) * L_SEQ) + HEAD_ROWS + (mm0 & (IMG_N - 1))) * DMODEL;
        int orow1 = (((mm1 >> 12) * L_SEQ) + HEAD_ROWS + (mm1 & (IMG_N - 1))) * DMODEL;
#pragma unroll
        for (int tn = 0; tn < 4; tn++) {
            int c = bn + wn * 32 + tn * 8 + tig * 2;
            float2 bsv = *(const float2*)&bias2[c];
            float2 x0 = *(const float2*)&x[orow0 + c];
            float2 x1 = *(const float2*)&x[orow1 + c];
            *(float2*)&out[orow0 + c] = make_float2(
                acc[tm][tn][0] + bsv.x + x0.x, acc[tm][tn][1] + bsv.y + x0.y);
            *(float2*)&out[orow1 + c] = make_float2(
                acc[tm][tn][2] + bsv.x + x1.x, acc[tm][tn][3] + bsv.y + x1.y);
        }
    }
}

// ---------------- depthwise causal conv1d + silu ----------------
__global__ void conv1d_kernel(const float* __restrict__ w, const float* __restrict__ bias) {
    int row = blockIdx.x;
    int b = row / L_SEQ;
    int l = row - b * L_SEQ;
    for (int c = threadIdx.x; c < CONVDIM; c += 256) {
        float acc = bias[c];
#pragma unroll
        for (int j = 0; j < 4; j++) {
            int ll = l - 3 + j;
            if (ll >= 0)
                acc += g_zx[(b * L_SEQ + ll) * DPROJ + DINNER + c] * w[c * 4 + j];
        }
        acc = acc / (1.f + expf(-acc));  // silu
        g_xbc[row * CONVDIM + c] = acc;
    }
}

// ---------------- dt = softplus(raw + bias), dA = exp(dt * -exp(A_log)) ----------------
__global__ void dtda_kernel(const float* __restrict__ dt_bias, const float* __restrict__ A_log) {
    int i = blockIdx.x * 256 + threadIdx.x;
    if (i >= ROWS * NHEADS) return;
    int row = i / NHEADS;
    int h = i - row * NHEADS;
    float v = g_zx[row * DPROJ + (DINNER + CONVDIM) + h] + dt_bias[h];
    float dtv = (v > 20.f) ? v : log1pf(expf(v));
    g_dt[i] = dtv;
    g_dA[i] = expf(-dtv * expf(A_log[h]));
}

// ---------------- selective scan ----------------
// grid (16, NHEADS, B), block 128 = 4 warps. warp -> p; lane -> 4 consecutive n.
__global__ __launch_bounds__(128) void scan_kernel(const float* __restrict__ Dskip) {
    int warp = threadIdx.x >> 5, lane = threadIdx.x & 31;
    int p = blockIdx.x * 4 + warp;
    int hh = blockIdx.y, b = blockIdx.z;
    int ch = hh * HEADDIM + p;
    float h0 = 0.f, h1 = 0.f, h2 = 0.f, h3 = 0.f;
    float Dh = Dskip[hh];
    int nb = lane * 4;
    const float* pdA = g_dA + (size_t)b * L_SEQ * NHEADS + hh;
    const float* pdt = g_dt + (size_t)b * L_SEQ * NHEADS + hh;
    const float* pxs = g_xbc + (size_t)b * L_SEQ * CONVDIM + ch;
    const float* pB  = g_xbc + (size_t)b * L_SEQ * CONVDIM + DINNER + nb;
    const float* pC  = pB + DSTATE;
    float* py = g_y + (size_t)b * L_SEQ * DINNER + ch;
    for (int t = 0; t < L_SEQ; ++t) {
        float dAt = *pdA;
        float dtt = *pdt;
        float xs = *pxs;
        float dtx = dtt * xs;
        float4 Bv = *(const float4*)pB;
        float4 Cv = *(const float4*)pC;
        h0 = h0 * dAt + dtx * Bv.x;
        h1 = h1 * dAt + dtx * Bv.y;
        h2 = h2 * dAt + dtx * Bv.z;
        h3 = h3 * dAt + dtx * Bv.w;
        float part = h0 * Cv.x + h1 * Cv.y + h2 * Cv.z + h3 * Cv.w;
#pragma unroll
        for (int o = 16; o; o >>= 1) part += __shfl_xor_sync(0xffffffffu, part, o);
        if (lane == 0) *py = part + Dh * xs;
        pdA += NHEADS; pdt += NHEADS;
        pxs += CONVDIM; pB += CONVDIM; pC += CONVDIM;
        py += DINNER;
    }
}

// ---------------- y = y * silu(z); RMSNorm; * norm_w ----------------
__global__ void gate_rms_kernel(const float* __restrict__ norm_w) {
    int row = blockIdx.x;
    int tid = threadIdx.x;
    __shared__ float sh[DINNER];
    float ss = 0.f;
#pragma unroll
    for (int it = 0; it < 6; ++it) {
        int c = tid + it * 256;
        float z = g_zx[row * DPROJ + c];
        float yv = g_y[row * DINNER + c];
        float t = yv * (z / (1.f + expf(-z)));
        sh[c] = t;
        ss += t * t;
    }
    float tot = blockSum256(ss);
    float sc = rsqrtf(tot * (1.f / 1536.f) + LN_EPS);
#pragma unroll
    for (int it = 0; it < 6; ++it) {
        int c = tid + it * 256;
        g_y[row * DINNER + c] = sh[c] * sc * norm_w[c];
    }
}

// ---------------- head rows: out = x + h ----------------
__global__ void head_add_kernel(const float* __restrict__ x, float* __restrict__ out) {
    int row = blockIdx.x;
    int b = row / HEAD_ROWS;
    int l = row - b * HEAD_ROWS;
    int g = (b * L_SEQ + l) * DMODEL;
    for (int c = threadIdx.x; c < DMODEL; c += 256)
        out[g + c] = x[g + c] + g_h[g + c];
}

// ---------------- conv2d weight transpose: w2t[tap*768+ci][co] ----------------
__global__ void wtrans_kernel(const float* __restrict__ w2) {
    int k = blockIdx.x;
    int tap = k / DMODEL;
    int ci = k - tap * DMODEL;
    const float* src = w2 + ci * 25 + tap;
    float* dst = g_w2t + k * DMODEL;
    for (int n = threadIdx.x; n < DMODEL; n += 256)
        dst[n] = src[n * K_CONV];
}

// ---------------- launch ----------------
extern "C" void kernel_launch(void* const* d_in, const int* in_sizes, int n_in,
                              void* d_out, int out_size) {
    const float* x         = (const float*)d_in[0];
    const float* ln1_w     = (const float*)d_in[1];
    const float* ln1_b     = (const float*)d_in[2];
    const float* in_proj_w = (const float*)d_in[3];
    const float* conv1d_w  = (const float*)d_in[4];
    const float* conv1d_b  = (const float*)d_in[5];
    const float* dt_bias   = (const float*)d_in[6];
    const float* A_log     = (const float*)d_in[7];
    const float* Dskip     = (const float*)d_in[8];
    const float* norm_w    = (const float*)d_in[9];
    const float* out_proj_w= (const float*)d_in[10];
    const float* ln2_w     = (const float*)d_in[11];
    const float* ln2_b     = (const float*)d_in[12];
    const float* conv2d_w  = (const float*)d_in[13];
    const float* conv2d_b  = (const float*)d_in[14];
    float* out = (float*)d_out;

    void *pu, *pzx, *py_, *ph;
    cudaGetSymbolAddress(&pu, g_u);
    cudaGetSymbolAddress(&pzx, g_zx);
    cudaGetSymbolAddress(&py_, g_y);
    cudaGetSymbolAddress(&ph, g_h);

    wtrans_kernel<<<K_CONV, 256>>>(conv2d_w);

    ln1_kernel<<<ROWS, 256>>>(x, ln1_w, ln1_b);

    sgemm_mma_kernel<<<dim3((DPROJ + 127) / 128, ROWS / 128), 256>>>(
        (const float*)pu, in_proj_w, (float*)pzx, ROWS, DPROJ, DMODEL);

    conv1d_kernel<<<ROWS, 256>>>(conv1d_w, conv1d_b);
    dtda_kernel<<<(ROWS * NHEADS + 255) / 256, 256>>>(dt_bias, A_log);

    scan_kernel<<<dim3(16, NHEADS, B_SZ), 128>>>(Dskip);

    gate_rms_kernel<<<ROWS, 256>>>(norm_w);

    sgemm_mma_kernel<<<dim3(DMODEL / 128, ROWS / 128), 256>>>(
        (const float*)py_, out_proj_w, (float*)ph, ROWS, DMODEL, DINNER);

    head_add_kernel<<<B_SZ * HEAD_ROWS, 256>>>(x, out);
    ln2_kernel<<<B_SZ * IMG_N, 256>>>(ln2_w, ln2_b);

    conv2d_mma_kernel<<<dim3(DMODEL / 128, (B_SZ * IMG_N) / 128), 256>>>(
        x, conv2d_b, out);
}

// round 5
// speedup vs baseline: 2.7436x; 1.2150x over previous
#include <cuda_runtime.h>
#include <math.h>
#include <stdint.h>

#define B_SZ 2
#define L_SEQ 4352
#define DMODEL 768
#define DINNER 1536
#define DSTATE 128
#define NHEADS 24
#define HEADDIM 64
#define CONVDIM 1792
#define DPROJ 3352
#define IMG_N 4096
#define ROWS (B_SZ * L_SEQ)            // 8704
#define HEAD_ROWS (L_SEQ - IMG_N)      // 256
#define LN_EPS 1e-5f
#define K_CONV (25 * DMODEL)           // 19200
#define SEG 17
#define TSEG 256                       // 17*256 = 4352

// ---------------- static scratch (no allocations allowed) ----------------
__device__ __align__(16) float g_u[ROWS * DMODEL];
__device__ __align__(16) float g_zx[ROWS * DPROJ];
__device__ __align__(16) float g_xbc[ROWS * CONVDIM];
__device__ float g_dt[ROWS * NHEADS];
__device__ float g_dA[ROWS * NHEADS];
__device__ float g_cums[ROWS * NHEADS];                   // within-segment cumprod of dA
__device__ __align__(16) float g_hseg[B_SZ * NHEADS * SEG * HEADDIM * DSTATE]; // 25.5MB
__device__ __align__(16) float g_y[ROWS * DINNER];
__device__ __align__(16) float g_h[ROWS * DMODEL];
__device__ __align__(16) float g_img[B_SZ * IMG_N * DMODEL];
__device__ __align__(16) float g_w2t[K_CONV * DMODEL];

// ---------------- helpers ----------------
__device__ __forceinline__ float blockSum256(float v) {
    __shared__ float sh[8];
    __syncthreads();
#pragma unroll
    for (int o = 16; o; o >>= 1) v += __shfl_xor_sync(0xffffffffu, v, o);
    if ((threadIdx.x & 31) == 0) sh[threadIdx.x >> 5] = v;
    __syncthreads();
    float tot = 0.f;
#pragma unroll
    for (int i = 0; i < 8; i++) tot += sh[i];
    return tot;
}

__device__ __forceinline__ uint32_t f2tf32(float x) {
    uint32_t r;
    asm("cvt.rna.tf32.f32 %0, %1;" : "=r"(r) : "f"(x));
    return r;
}

__device__ __forceinline__ void mma8(float* c, const uint32_t* a, const uint32_t* b) {
    asm("mma.sync.aligned.m16n8k8.row.col.f32.tf32.tf32.f32 "
        "{%0,%1,%2,%3},{%4,%5,%6,%7},{%8,%9},{%0,%1,%2,%3};"
        : "+f"(c[0]), "+f"(c[1]), "+f"(c[2]), "+f"(c[3])
        : "r"(a[0]), "r"(a[1]), "r"(a[2]), "r"(a[3]), "r"(b[0]), "r"(b[1]));
}

// ---------------- LayerNorm 1 (x -> g_u) ----------------
__global__ void ln1_kernel(const float* __restrict__ x, const float* __restrict__ w,
                           const float* __restrict__ b) {
    int row = blockIdx.x;
    int tid = threadIdx.x;
    const float* xr = x + row * DMODEL;
    float v0 = xr[tid], v1 = xr[tid + 256], v2 = xr[tid + 512];
    float mean = blockSum256(v0 + v1 + v2) * (1.f / 768.f);
    float d0 = v0 - mean, d1 = v1 - mean, d2 = v2 - mean;
    float var = blockSum256(d0 * d0 + d1 * d1 + d2 * d2) * (1.f / 768.f);
    float rs = rsqrtf(var + LN_EPS);
    float* o = g_u + row * DMODEL;
    o[tid]       = d0 * rs * w[tid]       + b[tid];
    o[tid + 256] = d1 * rs * w[tid + 256] + b[tid + 256];
    o[tid + 512] = d2 * rs * w[tid + 512] + b[tid + 512];
}

// ---------------- LayerNorm 2 (g_h tail -> g_img) ----------------
__global__ void ln2_kernel(const float* __restrict__ w, const float* __restrict__ b) {
    int m = blockIdx.x;
    int tid = threadIdx.x;
    int bb = m >> 12, pix = m & (IMG_N - 1);
    const float* xr = g_h + (bb * L_SEQ + HEAD_ROWS + pix) * DMODEL;
    float v0 = xr[tid], v1 = xr[tid + 256], v2 = xr[tid + 512];
    float mean = blockSum256(v0 + v1 + v2) * (1.f / 768.f);
    float d0 = v0 - mean, d1 = v1 - mean, d2 = v2 - mean;
    float var = blockSum256(d0 * d0 + d1 * d1 + d2 * d2) * (1.f / 768.f);
    float rs = rsqrtf(var + LN_EPS);
    float* o = g_img + m * DMODEL;
    o[tid]       = d0 * rs * w[tid]       + b[tid];
    o[tid + 256] = d1 * rs * w[tid + 256] + b[tid + 256];
    o[tid + 512] = d2 * rs * w[tid + 512] + b[tid + 512];
}

// ============================================================================
// TF32 tensor-core GEMM, double-buffered smem, one sync per k-tile.
// ============================================================================
__global__ __launch_bounds__(256) void sgemm_mma_kernel(
    const float* __restrict__ A, const float* __restrict__ Bm,
    float* __restrict__ C, int M, int N, int K) {
    __shared__ uint32_t As[2][128 * 20];
    __shared__ uint32_t Bs[2][16 * 136];
    int tid = threadIdx.x;
    int bm = blockIdx.y * 128, bn = blockIdx.x * 128;
    int arow = tid >> 1, acol = (tid & 1) << 3;
    int brow = tid >> 4, bcol = (tid & 15) << 3;
    int lane = tid & 31, w = tid >> 5;
    int wm = w >> 2, wn = w & 3;
    int gid = lane >> 2, tig = lane & 3;

    float acc[4][4][4];
#pragma unroll
    for (int i = 0; i < 4; i++)
#pragma unroll
        for (int j = 0; j < 4; j++)
#pragma unroll
            for (int q = 0; q < 4; q++) acc[i][j][q] = 0.f;

    const float* Ap = A + (bm + arow) * K + acol;
    int colb = bn + bcol;
    bool bok = (colb < N);
    const float* Bp0 = Bm + colb;

    float4 av0, av1, bv0, bv1;
    av0 = *(const float4*)(Ap);
    av1 = *(const float4*)(Ap + 4);
    {
        const float* Bp = Bp0 + brow * N;
        if (bok) { bv0 = *(const float4*)(Bp); bv1 = *(const float4*)(Bp + 4); }
        else { bv0 = bv1 = make_float4(0.f, 0.f, 0.f, 0.f); }
    }

    int ntiles = K >> 4;
    for (int kt = 0; kt < ntiles; ++kt) {
        int buf = kt & 1;
        uint32_t* as = &As[buf][arow * 20 + acol];
        as[0] = f2tf32(av0.x); as[1] = f2tf32(av0.y);
        as[2] = f2tf32(av0.z); as[3] = f2tf32(av0.w);
        as[4] = f2tf32(av1.x); as[5] = f2tf32(av1.y);
        as[6] = f2tf32(av1.z); as[7] = f2tf32(av1.w);
        uint32_t* bs = &Bs[buf][brow * 136 + bcol];
        bs[0] = f2tf32(bv0.x); bs[1] = f2tf32(bv0.y);
        bs[2] = f2tf32(bv0.z); bs[3] = f2tf32(bv0.w);
        bs[4] = f2tf32(bv1.x); bs[5] = f2tf32(bv1.y);
        bs[6] = f2tf32(bv1.z); bs[7] = f2tf32(bv1.w);
        __syncthreads();
        if (kt + 1 < ntiles) {
            int k0 = (kt + 1) << 4;
            av0 = *(const float4*)(Ap + k0);
            av1 = *(const float4*)(Ap + k0 + 4);
            const float* Bp = Bp0 + (k0 + brow) * N;
            if (bok) { bv0 = *(const float4*)(Bp); bv1 = *(const float4*)(Bp + 4); }
            else { bv0 = bv1 = make_float4(0.f, 0.f, 0.f, 0.f); }
        }
        const uint32_t* Asb = As[buf];
        const uint32_t* Bsb = Bs[buf];
#pragma unroll
        for (int ks = 0; ks < 2; ++ks) {
            int k8 = ks * 8;
            uint32_t af[4][4], bf[4][2];
#pragma unroll
            for (int tm = 0; tm < 4; tm++) {
                int r0 = wm * 64 + tm * 16 + gid;
                af[tm][0] = Asb[r0 * 20 + k8 + tig];
                af[tm][1] = Asb[(r0 + 8) * 20 + k8 + tig];
                af[tm][2] = Asb[r0 * 20 + k8 + tig + 4];
                af[tm][3] = Asb[(r0 + 8) * 20 + k8 + tig + 4];
            }
#pragma unroll
            for (int tn = 0; tn < 4; tn++) {
                int cl = wn * 32 + tn * 8 + gid;
                bf[tn][0] = Bsb[(k8 + tig) * 136 + cl];
                bf[tn][1] = Bsb[(k8 + tig + 4) * 136 + cl];
            }
#pragma unroll
            for (int tm = 0; tm < 4; tm++)
#pragma unroll
                for (int tn = 0; tn < 4; tn++)
                    mma8(acc[tm][tn], af[tm], bf[tn]);
        }
    }
#pragma unroll
    for (int tm = 0; tm < 4; tm++) {
        int r0 = bm + wm * 64 + tm * 16 + gid;
#pragma unroll
        for (int tn = 0; tn < 4; tn++) {
            int c = bn + wn * 32 + tn * 8 + tig * 2;
            if (c < N) {
                *(float2*)&C[r0 * N + c]       = make_float2(acc[tm][tn][0], acc[tm][tn][1]);
                *(float2*)&C[(r0 + 8) * N + c] = make_float2(acc[tm][tn][2], acc[tm][tn][3]);
            }
        }
    }
}

// conv2d 5x5 SAME implicit GEMM on tensor cores + bias + residual.
__global__ __launch_bounds__(256) void conv2d_mma_kernel(
    const float* __restrict__ x, const float* __restrict__ bias2,
    float* __restrict__ out) {
    __shared__ uint32_t As[2][128 * 20];
    __shared__ uint32_t Bs[2][16 * 136];
    int tid = threadIdx.x;
    int bm = blockIdx.y * 128, bn = blockIdx.x * 128;
    int arow = tid >> 1, acol = (tid & 1) << 3;
    int brow = tid >> 4, bcol = (tid & 15) << 3;
    int lane = tid & 31, w = tid >> 5;
    int wm = w >> 2, wn = w & 3;
    int gid = lane >> 2, tig = lane & 3;

    float acc[4][4][4];
#pragma unroll
    for (int i = 0; i < 4; i++)
#pragma unroll
        for (int j = 0; j < 4; j++)
#pragma unroll
            for (int q = 0; q < 4; q++) acc[i][j][q] = 0.f;

    int m = bm + arow;
    int bi = m >> 12;
    int pix = m & (IMG_N - 1);
    int py = pix >> 6, px = pix & 63;

    int ky = 0, kx = 0;
    int iy = py - 2, ix = px - 2;
    bool ok = (iy >= 0) && (iy < 64) && (ix >= 0) && (ix < 64);
    const float* Abase = &g_img[((bi << 12) + (iy << 6) + ix) * DMODEL + acol];
    int aoff = 0;
    const float* Bp = g_w2t + brow * DMODEL + bn + bcol;

    float4 av0, av1, bv0, bv1;
    if (ok) { av0 = *(const float4*)(Abase); av1 = *(const float4*)(Abase + 4); }
    else { av0 = av1 = make_float4(0.f, 0.f, 0.f, 0.f); }
    bv0 = *(const float4*)(Bp);
    bv1 = *(const float4*)(Bp + 4);

    const int NTILES = 25 * (DMODEL / 16);   // 1200
    for (int kt = 0; kt < NTILES; ++kt) {
        int buf = kt & 1;
        uint32_t* as = &As[buf][arow * 20 + acol];
        as[0] = f2tf32(av0.x); as[1] = f2tf32(av0.y);
        as[2] = f2tf32(av0.z); as[3] = f2tf32(av0.w);
        as[4] = f2tf32(av1.x); as[5] = f2tf32(av1.y);
        as[6] = f2tf32(av1.z); as[7] = f2tf32(av1.w);
        uint32_t* bs = &Bs[buf][brow * 136 + bcol];
        bs[0] = f2tf32(bv0.x); bs[1] = f2tf32(bv0.y);
        bs[2] = f2tf32(bv0.z); bs[3] = f2tf32(bv0.w);
        bs[4] = f2tf32(bv1.x); bs[5] = f2tf32(bv1.y);
        bs[6] = f2tf32(bv1.z); bs[7] = f2tf32(bv1.w);
        __syncthreads();
        if (kt + 1 < NTILES) {
            aoff += 16;
            if (aoff == DMODEL) {
                aoff = 0;
                kx++;
                if (kx == 5) { kx = 0; ky++; }
                iy = py + ky - 2; ix = px + kx - 2;
                ok = (iy >= 0) && (iy < 64) && (ix >= 0) && (ix < 64);
                Abase = &g_img[((bi << 12) + (iy << 6) + ix) * DMODEL + acol];
            }
            if (ok) { av0 = *(const float4*)(Abase + aoff); av1 = *(const float4*)(Abase + aoff + 4); }
            else { av0 = av1 = make_float4(0.f, 0.f, 0.f, 0.f); }
            Bp += 16 * DMODEL;
            bv0 = *(const float4*)(Bp);
            bv1 = *(const float4*)(Bp + 4);
        }
        const uint32_t* Asb = As[buf];
        const uint32_t* Bsb = Bs[buf];
#pragma unroll
        for (int ks = 0; ks < 2; ++ks) {
            int k8 = ks * 8;
            uint32_t af[4][4], bf[4][2];
#pragma unroll
            for (int tm = 0; tm < 4; tm++) {
                int r0 = wm * 64 + tm * 16 + gid;
                af[tm][0] = Asb[r0 * 20 + k8 + tig];
                af[tm][1] = Asb[(r0 + 8) * 20 + k8 + tig];
                af[tm][2] = Asb[r0 * 20 + k8 + tig + 4];
                af[tm][3] = Asb[(r0 + 8) * 20 + k8 + tig + 4];
            }
#pragma unroll
            for (int tn = 0; tn < 4; tn++) {
                int cl = wn * 32 + tn * 8 + gid;
                bf[tn][0] = Bsb[(k8 + tig) * 136 + cl];
                bf[tn][1] = Bsb[(k8 + tig + 4) * 136 + cl];
            }
#pragma unroll
            for (int tm = 0; tm < 4; tm++)
#pragma unroll
                for (int tn = 0; tn < 4; tn++)
                    mma8(acc[tm][tn], af[tm], bf[tn]);
        }
    }
#pragma unroll
    for (int tm = 0; tm < 4; tm++) {
        int mm0 = bm + wm * 64 + tm * 16 + gid;
        int mm1 = mm0 + 8;
        int orow0 = (((mm0 >> 12) * L_SEQ) + HEAD_ROWS + (mm0 & (IMG_N - 1))) * DMODEL;
        int orow1 = (((mm1 >> 12) * L_SEQ) + HEAD_ROWS + (mm1 & (IMG_N - 1))) * DMODEL;
#pragma unroll
        for (int tn = 0; tn < 4; tn++) {
            int c = bn + wn * 32 + tn * 8 + tig * 2;
            float2 bsv = *(const float2*)&bias2[c];
            float2 x0 = *(const float2*)&x[orow0 + c];
            float2 x1 = *(const float2*)&x[orow1 + c];
            *(float2*)&out[orow0 + c] = make_float2(
                acc[tm][tn][0] + bsv.x + x0.x, acc[tm][tn][1] + bsv.y + x0.y);
            *(float2*)&out[orow1 + c] = make_float2(
                acc[tm][tn][2] + bsv.x + x1.x, acc[tm][tn][3] + bsv.y + x1.y);
        }
    }
}

// ---------------- depthwise causal conv1d + silu ----------------
__global__ void conv1d_kernel(const float* __restrict__ w, const float* __restrict__ bias) {
    int row = blockIdx.x;
    int b = row / L_SEQ;
    int l = row - b * L_SEQ;
    for (int c = threadIdx.x; c < CONVDIM; c += 256) {
        float acc = bias[c];
#pragma unroll
        for (int j = 0; j < 4; j++) {
            int ll = l - 3 + j;
            if (ll >= 0)
                acc += g_zx[(b * L_SEQ + ll) * DPROJ + DINNER + c] * w[c * 4 + j];
        }
        acc = acc / (1.f + expf(-acc));  // silu
        g_xbc[row * CONVDIM + c] = acc;
    }
}

// ---------------- dt = softplus(raw + bias), dA = exp(dt * -exp(A_log)) ----------------
__global__ void dtda_kernel(const float* __restrict__ dt_bias, const float* __restrict__ A_log) {
    int i = blockIdx.x * 256 + threadIdx.x;
    if (i >= ROWS * NHEADS) return;
    int row = i / NHEADS;
    int h = i - row * NHEADS;
    float v = g_zx[row * DPROJ + (DINNER + CONVDIM) + h] + dt_bias[h];
    float dtv = (v > 20.f) ? v : log1pf(expf(v));
    g_dt[i] = dtv;
    g_dA[i] = expf(-dtv * expf(A_log[h]));
}

// ---------------- selective scan pass 1: per-segment local scan ----------------
// grid (SEG, NHEADS, B), block 64. lane = p. Full 128-state in registers.
// Writes local y, per-t cumprod(dA), and local end-state.
__global__ __launch_bounds__(64) void scan_seg_kernel(const float* __restrict__ Dskip) {
    int p = threadIdx.x;
    int seg = blockIdx.x, hh = blockIdx.y, b = blockIdx.z;
    float4 h[32];
#pragma unroll
    for (int i = 0; i < 32; i++) h[i] = make_float4(0.f, 0.f, 0.f, 0.f);
    float cum = 1.f;
    float Dh = Dskip[hh];
    size_t r0 = (size_t)b * L_SEQ + seg * TSEG;
    const float* pxb = g_xbc + r0 * CONVDIM;
    const float* pda = g_dA + r0 * NHEADS + hh;
    const float* pdt = g_dt + r0 * NHEADS + hh;
    float* py = g_y + r0 * DINNER + hh * HEADDIM + p;
    float* pc = g_cums + r0 * NHEADS + hh;
    for (int t = 0; t < TSEG; ++t) {
        float dAt = *pda;
        float dtt = *pdt;
        float xs = pxb[hh * HEADDIM + p];
        float dtx = dtt * xs;
        cum *= dAt;
        float y = Dh * xs;
        const float4* Bv = (const float4*)(pxb + DINNER);
        const float4* Cv = (const float4*)(pxb + DINNER + DSTATE);
#pragma unroll
        for (int i = 0; i < 32; i++) {
            float4 Bb = Bv[i];
            float4 Cc = Cv[i];
            h[i].x = h[i].x * dAt + dtx * Bb.x;
            h[i].y = h[i].y * dAt + dtx * Bb.y;
            h[i].z = h[i].z * dAt + dtx * Bb.z;
            h[i].w = h[i].w * dAt + dtx * Bb.w;
            y += h[i].x * Cc.x + h[i].y * Cc.y + h[i].z * Cc.z + h[i].w * Cc.w;
        }
        *py = y;
        if (p == 0) *pc = cum;
        pxb += CONVDIM; pda += NHEADS; pdt += NHEADS; py += DINNER; pc += NHEADS;
    }
    float* hs = g_hseg + (((size_t)(b * NHEADS + hh) * SEG + seg) * HEADDIM + p) * DSTATE;
#pragma unroll
    for (int i = 0; i < 32; i++) *(float4*)(hs + i * 4) = h[i];
}

// ---------------- scan pass 2: carry propagation across segments ----------------
// grid (B*NHEADS), block 256. Converts local end-states into start-states in place.
__global__ void carry_kernel() {
    int bh = blockIdx.x;
    int b = bh / NHEADS, hh = bh - b * NHEADS;
    __shared__ float dAseg[SEG];
    if (threadIdx.x < SEG) {
        size_t t = (size_t)b * L_SEQ + (threadIdx.x + 1) * TSEG - 1;
        dAseg[threadIdx.x] = g_cums[t * NHEADS + hh];
    }
    __syncthreads();
    float* base = g_hseg + (size_t)bh * SEG * HEADDIM * DSTATE;
    for (int e = threadIdx.x; e < HEADDIM * DSTATE; e += 256) {
        float carry = 0.f;
#pragma unroll
        for (int s = 0; s < SEG; s++) {
            float* ptr = base + (size_t)s * HEADDIM * DSTATE + e;
            float tmp = *ptr;
            *ptr = carry;                       // now the start state H(s)
            carry = dAseg[s] * carry + tmp;
        }
    }
}

// ---------------- scan pass 3: y_t += cum_t * (C_t . H_start) ----------------
// grid (SEG-1, NHEADS, B), block 64 (segment 0 has H=0).
__global__ __launch_bounds__(64) void scan_fix_kernel() {
    int p = threadIdx.x;
    int seg = blockIdx.x + 1, hh = blockIdx.y, b = blockIdx.z;
    float4 h[32];
    const float* hs = g_hseg + (((size_t)(b * NHEADS + hh) * SEG + seg) * HEADDIM + p) * DSTATE;
#pragma unroll
    for (int i = 0; i < 32; i++) h[i] = *(const float4*)(hs + i * 4);
    size_t r0 = (size_t)b * L_SEQ + seg * TSEG;
    const float* pC = g_xbc + r0 * CONVDIM + DINNER + DSTATE;
    const float* pc = g_cums + r0 * NHEADS + hh;
    float* py = g_y + r0 * DINNER + hh * HEADDIM + p;
    for (int t = 0; t < TSEG; ++t) {
        float cumt = *pc;
        float y = 0.f;
        const float4* Cv = (const float4*)pC;
#pragma unroll
        for (int i = 0; i < 32; i++) {
            float4 Cc = Cv[i];
            y += h[i].x * Cc.x + h[i].y * Cc.y + h[i].z * Cc.z + h[i].w * Cc.w;
        }
        *py += cumt * y;
        pC += CONVDIM; pc += NHEADS; py += DINNER;
    }
}

// ---------------- y = y * silu(z); RMSNorm; * norm_w ----------------
__global__ void gate_rms_kernel(const float* __restrict__ norm_w) {
    int row = blockIdx.x;
    int tid = threadIdx.x;
    __shared__ float sh[DINNER];
    float ss = 0.f;
#pragma unroll
    for (int it = 0; it < 6; ++it) {
        int c = tid + it * 256;
        float z = g_zx[row * DPROJ + c];
        float yv = g_y[row * DINNER + c];
        float t = yv * (z / (1.f + expf(-z)));
        sh[c] = t;
        ss += t * t;
    }
    float tot = blockSum256(ss);
    float sc = rsqrtf(tot * (1.f / 1536.f) + LN_EPS);
#pragma unroll
    for (int it = 0; it < 6; ++it) {
        int c = tid + it * 256;
        g_y[row * DINNER + c] = sh[c] * sc * norm_w[c];
    }
}

// ---------------- head rows: out = x + h ----------------
__global__ void head_add_kernel(const float* __restrict__ x, float* __restrict__ out) {
    int row = blockIdx.x;
    int b = row / HEAD_ROWS;
    int l = row - b * HEAD_ROWS;
    int g = (b * L_SEQ + l) * DMODEL;
    for (int c = threadIdx.x; c < DMODEL; c += 256)
        out[g + c] = x[g + c] + g_h[g + c];
}

// ---------------- conv2d weight transpose (tiled, coalesced both sides) -----
// w2t[(k%25)*768 + k/25][co] = w2[co][k], k = ci*25+tap in [0,19200)
__global__ void wtrans_kernel(const float* __restrict__ w2) {
    __shared__ float tile[32][33];
    int k0 = blockIdx.x * 32, c0 = blockIdx.y * 32;
    int tx = threadIdx.x, ty = threadIdx.y;       // block (32, 8)
#pragma unroll
    for (int i = 0; i < 4; i++)
        tile[ty + 8 * i][tx] = w2[(size_t)(c0 + ty + 8 * i) * K_CONV + k0 + tx];
    __syncthreads();
#pragma unroll
    for (int i = 0; i < 4; i++) {
        int k = k0 + ty + 8 * i;
        int tap = k % 25, ci = k / 25;
        g_w2t[(size_t)(tap * DMODEL + ci) * DMODEL + c0 + tx] = tile[tx][ty + 8 * i];
    }
}

// ---------------- launch ----------------
extern "C" void kernel_launch(void* const* d_in, const int* in_sizes, int n_in,
                              void* d_out, int out_size) {
    const float* x         = (const float*)d_in[0];
    const float* ln1_w     = (const float*)d_in[1];
    const float* ln1_b     = (const float*)d_in[2];
    const float* in_proj_w = (const float*)d_in[3];
    const float* conv1d_w  = (const float*)d_in[4];
    const float* conv1d_b  = (const float*)d_in[5];
    const float* dt_bias   = (const float*)d_in[6];
    const float* A_log     = (const float*)d_in[7];
    const float* Dskip     = (const float*)d_in[8];
    const float* norm_w    = (const float*)d_in[9];
    const float* out_proj_w= (const float*)d_in[10];
    const float* ln2_w     = (const float*)d_in[11];
    const float* ln2_b     = (const float*)d_in[12];
    const float* conv2d_w  = (const float*)d_in[13];
    const float* conv2d_b  = (const float*)d_in[14];
    float* out = (float*)d_out;

    void *pu, *pzx, *py_, *ph;
    cudaGetSymbolAddress(&pu, g_u);
    cudaGetSymbolAddress(&pzx, g_zx);
    cudaGetSymbolAddress(&py_, g_y);
    cudaGetSymbolAddress(&ph, g_h);

    wtrans_kernel<<<dim3(K_CONV / 32, DMODEL / 32), dim3(32, 8)>>>(conv2d_w);

    ln1_kernel<<<ROWS, 256>>>(x, ln1_w, ln1_b);

    sgemm_mma_kernel<<<dim3((DPROJ + 127) / 128, ROWS / 128), 256>>>(
        (const float*)pu, in_proj_w, (float*)pzx, ROWS, DPROJ, DMODEL);

    conv1d_kernel<<<ROWS, 256>>>(conv1d_w, conv1d_b);
    dtda_kernel<<<(ROWS * NHEADS + 255) / 256, 256>>>(dt_bias, A_log);

    scan_seg_kernel<<<dim3(SEG, NHEADS, B_SZ), 64>>>(Dskip);
    carry_kernel<<<B_SZ * NHEADS, 256>>>();
    scan_fix_kernel<<<dim3(SEG - 1, NHEADS, B_SZ), 64>>>();

    gate_rms_kernel<<<ROWS, 256>>>(norm_w);

    sgemm_mma_kernel<<<dim3(DMODEL / 128, ROWS / 128), 256>>>(
        (const float*)py_, out_proj_w, (float*)ph, ROWS, DMODEL, DINNER);

    head_add_kernel<<<B_SZ * HEAD_ROWS, 256>>>(x, out);
    ln2_kernel<<<B_SZ * IMG_N, 256>>>(ln2_w, ln2_b);

    conv2d_mma_kernel<<<dim3(DMODEL / 128, (B_SZ * IMG_N) / 128), 256>>>(
        x, conv2d_b, out);
}